// round 10
// baseline (speedup 1.0000x reference)
#include <cuda_runtime.h>
#include <cuda_fp16.h>
#include <cstdint>
#include <cstddef>

// ----------------------------------------------------------------------------
// Problem constants
// ----------------------------------------------------------------------------
#define BB   512
#define QQ   32768
#define DD   256
#define ROWL 32769            // 1 + Q
#define NCOMBO 8

__constant__ int d_CI[8] = {0, 0, 0, 1, 1, 2, 2, 3};
__constant__ int d_CJ[8] = {1, 2, 3, 0, 2, 0, 1, 0};

// ----------------------------------------------------------------------------
// Scratch (device globals; no allocation allowed)
// ----------------------------------------------------------------------------
__device__ __align__(16) __half g_m_h[4u * QQ * DD];   // 64 MB fp16 mem
__device__ __align__(16) __half g_x_h[4 * BB * DD];    // fp16 X
__device__ float g_scale[NCOMBO * BB];                 // 1/(ni*nj*T)

// ----------------------------------------------------------------------------
// PTX helpers (sm_103-safe: mma.sync / ldmatrix / cp.async only)
// ----------------------------------------------------------------------------
__device__ __forceinline__ uint32_t smem_to_u32(const void* p) {
    uint32_t a;
    asm("{ .reg .u64 t; cvta.to.shared.u64 t, %1; cvt.u32.u64 %0, t; }" : "=r"(a) : "l"(p));
    return a;
}

__device__ __forceinline__ void cp_async16(uint32_t saddr, const void* gaddr) {
    asm volatile("cp.async.cg.shared.global [%0], [%1], 16;" :: "r"(saddr), "l"(gaddr));
}
__device__ __forceinline__ void cp_commit() {
    asm volatile("cp.async.commit_group;" ::: "memory");
}
template <int N>
__device__ __forceinline__ void cp_wait() {
    asm volatile("cp.async.wait_group %0;" :: "n"(N) : "memory");
}

__device__ __forceinline__ void ldsm_x4(uint32_t* r, uint32_t addr) {
    asm volatile("ldmatrix.sync.aligned.m8n8.x4.shared.b16 {%0,%1,%2,%3}, [%4];"
                 : "=r"(r[0]), "=r"(r[1]), "=r"(r[2]), "=r"(r[3]) : "r"(addr));
}

__device__ __forceinline__ void mma_f16(float* d, const uint32_t* a, const uint32_t* b) {
    asm volatile(
        "mma.sync.aligned.m16n8k16.row.col.f32.f16.f16.f32 "
        "{%0,%1,%2,%3}, {%4,%5,%6,%7}, {%8,%9}, {%0,%1,%2,%3};"
        : "+f"(d[0]), "+f"(d[1]), "+f"(d[2]), "+f"(d[3])
        : "r"(a[0]), "r"(a[1]), "r"(a[2]), "r"(a[3]), "r"(b[0]), "r"(b[1]));
}

// ----------------------------------------------------------------------------
// Small helpers
// ----------------------------------------------------------------------------
__device__ __forceinline__ const float* sel4(int v, const float* a, const float* b,
                                             const float* c, const float* d) {
    return v == 0 ? a : (v == 1 ? b : (v == 2 ? c : d));
}

// ----------------------------------------------------------------------------
// k_prep: merged prep (all parts independent):
//   blocks [0, 16384)      : mem -> fp16 scratch (v = b>>12)
//   blocks [16384, 16512)  : X -> fp16 scratch
//   blocks [16512, 17024)  : Y -> tail of new_mem
//   blocks [17024, 17536)  : self-dots + norms + scales (one warp per row)
// ----------------------------------------------------------------------------
__global__ void k_prep(const float* __restrict__ x0, const float* __restrict__ x1,
                       const float* __restrict__ x2, const float* __restrict__ x3,
                       const float* __restrict__ y0, const float* __restrict__ y1,
                       const float* __restrict__ y2, const float* __restrict__ y3,
                       const float* __restrict__ m0, const float* __restrict__ m1,
                       const float* __restrict__ m2, const float* __restrict__ m3,
                       float* __restrict__ out, float* __restrict__ out_mem) {
    const int b = blockIdx.x;
    const int t = threadIdx.x;
    if (b < 16384) {
        // mem -> fp16
        int v = b >> 12, bx = b & 4095;
        int idx = (bx * 256 + t) * 2;                 // float4 index, 2 per thread
        const float4* src = reinterpret_cast<const float4*>(sel4(v, m0, m1, m2, m3));
        float4 f0 = src[idx + 0];
        float4 f1 = src[idx + 1];
        __half2 h0 = __floats2half2_rn(f0.x, f0.y);
        __half2 h1 = __floats2half2_rn(f0.z, f0.w);
        __half2 h2 = __floats2half2_rn(f1.x, f1.y);
        __half2 h3 = __floats2half2_rn(f1.z, f1.w);
        uint4 pk;
        pk.x = *reinterpret_cast<uint32_t*>(&h0);
        pk.y = *reinterpret_cast<uint32_t*>(&h1);
        pk.z = *reinterpret_cast<uint32_t*>(&h2);
        pk.w = *reinterpret_cast<uint32_t*>(&h3);
        reinterpret_cast<uint4*>(g_m_h + (size_t)v * QQ * DD)[idx / 2] = pk;
    } else if (b < 16512) {
        // X -> fp16
        int r = b - 16384;
        int v = r >> 5, bx = r & 31;
        int idx = bx * 1024 + t * 4;                  // float4 index
        const float4* src = reinterpret_cast<const float4*>(sel4(v, x0, x1, x2, x3));
        uint4 pk[2];
#pragma unroll
        for (int g = 0; g < 2; g++) {
            float4 f0 = src[idx + g * 2 + 0];
            float4 f1 = src[idx + g * 2 + 1];
            __half2 h0 = __floats2half2_rn(f0.x, f0.y);
            __half2 h1 = __floats2half2_rn(f0.z, f0.w);
            __half2 h2 = __floats2half2_rn(f1.x, f1.y);
            __half2 h3 = __floats2half2_rn(f1.z, f1.w);
            pk[g].x = *reinterpret_cast<uint32_t*>(&h0);
            pk[g].y = *reinterpret_cast<uint32_t*>(&h1);
            pk[g].z = *reinterpret_cast<uint32_t*>(&h2);
            pk[g].w = *reinterpret_cast<uint32_t*>(&h3);
        }
        uint4* dst = reinterpret_cast<uint4*>(g_x_h + (size_t)v * BB * DD);
        dst[idx / 2 + 0] = pk[0];
        dst[idx / 2 + 1] = pk[1];
    } else if (b < 17024) {
        // Y -> tail of new_mem
        int r = b - 16512;
        int v = r >> 7, bx = r & 127;
        int idx = bx * 256 + t;                       // < 32768 float4 per view
        float4 f = reinterpret_cast<const float4*>(sel4(v, y0, y1, y2, y3))[idx];
        reinterpret_cast<float4*>(out_mem)[(size_t)v * (QQ * DD / 4) + (size_t)(QQ - BB) * (DD / 4) + idx] = f;
    } else {
        // self-dots + norms + scales
        int gw = (b - 17024) * 8 + (t >> 5);          // < 4096
        int lane = t & 31;
        int c = gw >> 9, row = gw & (BB - 1);
        int i = d_CI[c], j = d_CJ[c];
        const float* xi = sel4(i, x0, x1, x2, x3) + (size_t)row * DD;
        const float* xj = sel4(j, x0, x1, x2, x3) + (size_t)row * DD;
        float s = 0.f, ni = 0.f, nj = 0.f;
#pragma unroll
        for (int k = 0; k < 8; k++) {
            float a = xi[lane + k * 32], d = xj[lane + k * 32];
            s = fmaf(a, d, s);
            ni = fmaf(a, a, ni);
            nj = fmaf(d, d, nj);
        }
#pragma unroll
        for (int o = 16; o; o >>= 1) {
            s  += __shfl_xor_sync(0xffffffffu, s, o);
            ni += __shfl_xor_sync(0xffffffffu, ni, o);
            nj += __shfl_xor_sync(0xffffffffu, nj, o);
        }
        if (lane == 0) {
            float sc = 1.0f / (sqrtf(ni) * sqrtf(nj) * 0.07f);
            g_scale[c * BB + row] = sc;
            out[(size_t)c * BB * ROWL + (size_t)row * ROWL] = __expf(s * sc);
        }
    }
}

// ----------------------------------------------------------------------------
// k_gemm: single-pass fp16 mma.sync GEMM + smem-transposed exp epilogue
//         + fused FIFO copy. Higher occupancy variant.
// Block tile M=128 x N=64, K=256 in 4 chunks of 64, cp.async double-buffered.
// 8 warps: 2 (m) x 4 (n); warp tile 64x16; 3 CTAs/SM (<=84 regs).
// ----------------------------------------------------------------------------
#define TS_ROWB   144
#define TILE_A    (128 * TS_ROWB)          // 18432
#define TILE_BS   (64 * TS_ROWB)           // 9216
#define BUF_B     (TILE_A + TILE_BS)       // 27648
#define GEMM_SMEM (2 * BUF_B)              // 55296 (>= 128*68*4 = 34816)
#define EPI_STRIDE 68
#define CPY_PER_CTA 504
#define CPY_PER_VIEW ((QQ - BB) * DD / 4)  // 2064384 float4

__global__ void __launch_bounds__(256, 3) k_gemm(float* __restrict__ out,
                                                 const float* __restrict__ m0,
                                                 const float* __restrict__ m1,
                                                 const float* __restrict__ m2,
                                                 const float* __restrict__ m3,
                                                 float* __restrict__ out_mem) {
    extern __shared__ char smem[];
    const uint32_t sb = smem_to_u32(smem);
    const int tid = threadIdx.x, lane = tid & 31, wid = tid >> 5;
    const int wm = wid & 1, wn = wid >> 1;
    const int cm = blockIdx.x;
    const int c = cm >> 2, mtile = cm & 3, ntile = blockIdx.y;   // ntile < 512
    const int i = d_CI[c], j = d_CJ[c];

    const __half* srcA = g_x_h + ((size_t)i * BB + mtile * 128) * DD;
    const __half* srcB = g_m_h + ((size_t)j * QQ + (size_t)ntile * 64) * DD;

    // A: 4 slots (1024 x 16B), B: 2 slots (512 x 16B)
    const int l_seg = tid & 7;

    auto issue_chunk = [&](int kc, int buf) {
        uint32_t sbase = sb + buf * BUF_B;
#pragma unroll
        for (int r = 0; r < 4; r++) {
            int idx = tid + r * 256;
            int row = idx >> 3;
            const __half* gA = srcA + (size_t)row * DD + kc * 64 + l_seg * 8;
            cp_async16(sbase + row * TS_ROWB + l_seg * 16, gA);
        }
#pragma unroll
        for (int r = 0; r < 2; r++) {
            int idx = tid + r * 256;
            int row = idx >> 3;
            const __half* gB = srcB + (size_t)row * DD + kc * 64 + l_seg * 8;
            cp_async16(sbase + TILE_A + row * TS_ROWB + l_seg * 16, gB);
        }
        cp_commit();
    };

    issue_chunk(0, 0);

    // ---- fused FIFO shift copy (overlaps with first cp.async chunk) ----
    {
        const int gid = blockIdx.y * 32 + blockIdx.x;          // 0..16383
        int u0 = gid * CPY_PER_CTA + tid;
#pragma unroll
        for (int g = 0; g < 2; g++) {
            int u = u0 + g * 256;
            if (g < 1 || u < (gid + 1) * CPY_PER_CTA) {
                int v = u / CPY_PER_VIEW;
                int rem = u - v * CPY_PER_VIEW;
                const float4* s4 = reinterpret_cast<const float4*>(sel4(v, m0, m1, m2, m3));
                float4 f = s4[BB * (DD / 4) + rem];
                reinterpret_cast<float4*>(out_mem)[(size_t)v * (QQ * DD / 4) + rem] = f;
            }
        }
    }

    float acc[4][2][4];
#pragma unroll
    for (int a = 0; a < 4; a++)
#pragma unroll
        for (int b = 0; b < 2; b++)
#pragma unroll
            for (int k = 0; k < 4; k++) acc[a][b][k] = 0.f;

    // ldmatrix base offsets (within a buffer)
    const uint32_t a_lane_off = (uint32_t)((lane & 15) * TS_ROWB + (lane >> 4) * 16);
    const uint32_t b_lane_off = (uint32_t)(((lane & 7) + ((lane >> 4) << 3)) * TS_ROWB
                                           + (((lane >> 3) & 1) * 16));

#pragma unroll 1
    for (int kc = 0; kc < 4; kc++) {
        if (kc < 3) issue_chunk(kc + 1, (kc + 1) & 1);
        if (kc < 3) cp_wait<1>(); else cp_wait<0>();
        __syncthreads();

        const uint32_t bufb = sb + (kc & 1) * BUF_B;
        const uint32_t aT = bufb + (wm * 64) * TS_ROWB + a_lane_off;
        const uint32_t bT = bufb + TILE_A + (wn * 16) * TS_ROWB + b_lane_off;

#pragma unroll
        for (int step = 0; step < 4; step++) {
            const uint32_t koff = step * 32;   // 16 fp16 = 32 bytes
            uint32_t bh[4];
            ldsm_x4(bh, bT + koff);                            // n 0-15 (local)
#pragma unroll
            for (int mi = 0; mi < 4; mi++) {
                uint32_t ah[4];
                ldsm_x4(ah, aT + mi * 16 * TS_ROWB + koff);
#pragma unroll
                for (int ni = 0; ni < 2; ni++)
                    mma_f16(acc[mi][ni], ah, bh + ni * 2);
            }
        }
        __syncthreads();
    }

    // ---- Epilogue: exp in regs -> smem stage (128 x 68 fp32) -> coalesced STG
    float* sout = reinterpret_cast<float*>(smem);
    const int r0 = lane >> 2;
    const int cpair = (lane & 3) * 2;
#pragma unroll
    for (int mi = 0; mi < 4; mi++) {
        const int lrow0 = wm * 64 + mi * 16 + r0;    // local row 0..127
        const int grow0 = mtile * 128 + lrow0;
        const float scl0 = g_scale[c * BB + grow0];
        const float scl1 = g_scale[c * BB + grow0 + 8];
#pragma unroll
        for (int ni = 0; ni < 2; ni++) {
            const int col = wn * 16 + ni * 8 + cpair;
            sout[lrow0 * EPI_STRIDE + col + 0]       = __expf(acc[mi][ni][0] * scl0);
            sout[lrow0 * EPI_STRIDE + col + 1]       = __expf(acc[mi][ni][1] * scl0);
            sout[(lrow0 + 8) * EPI_STRIDE + col + 0] = __expf(acc[mi][ni][2] * scl1);
            sout[(lrow0 + 8) * EPI_STRIDE + col + 1] = __expf(acc[mi][ni][3] * scl1);
        }
    }
    __syncthreads();

    // drain: warp writes 32 consecutive floats per instruction (coalesced)
    const size_t ocol = 1 + (size_t)ntile * 64;
#pragma unroll 8
    for (int it = 0; it < 32; it++) {
        int flat = it * 256 + tid;                 // 0..8191
        int row = flat >> 6;
        int col = flat & 63;
        float v = sout[row * EPI_STRIDE + col];
        int grow = mtile * 128 + row;
        out[((size_t)c * BB + grow) * ROWL + ocol + col] = v;
    }
}

// ----------------------------------------------------------------------------
// kernel_launch — input order detected from in_sizes (interleaved vs grouped)
// ----------------------------------------------------------------------------
extern "C" void kernel_launch(void* const* d_in, const int* in_sizes, int n_in,
                              void* d_out, int out_size) {
    (void)n_in; (void)out_size;
    const float* x[4]; const float* y[4]; const float* m[4];
    const bool interleaved = (in_sizes[2] == QQ * DD);
    for (int v = 0; v < 4; v++) {
        if (interleaved) {
            x[v] = (const float*)d_in[3 * v + 0];
            y[v] = (const float*)d_in[3 * v + 1];
            m[v] = (const float*)d_in[3 * v + 2];
        } else {
            x[v] = (const float*)d_in[v];
            y[v] = (const float*)d_in[4 + v];
            m[v] = (const float*)d_in[8 + v];
        }
    }
    float* out = (float*)d_out;
    float* out_mem = out + (size_t)NCOMBO * BB * ROWL;

    cudaFuncSetAttribute(k_gemm, cudaFuncAttributeMaxDynamicSharedMemorySize, GEMM_SMEM);

    k_prep<<<17536, 256>>>(x[0], x[1], x[2], x[3],
                           y[0], y[1], y[2], y[3],
                           m[0], m[1], m[2], m[3], out, out_mem);
    k_gemm<<<dim3(32, 512), 256, GEMM_SMEM>>>(out, m[0], m[1], m[2], m[3], out_mem);
}

// round 11
// speedup vs baseline: 1.0682x; 1.0682x over previous
#include <cuda_runtime.h>
#include <cuda_fp16.h>
#include <cstdint>
#include <cstddef>

// ----------------------------------------------------------------------------
// Problem constants
// ----------------------------------------------------------------------------
#define BB   512
#define QQ   32768
#define DD   256
#define ROWL 32769            // 1 + Q
#define NCOMBO 8

__constant__ int d_CI[8] = {0, 0, 0, 1, 1, 2, 2, 3};
__constant__ int d_CJ[8] = {1, 2, 3, 0, 2, 0, 1, 0};

// ----------------------------------------------------------------------------
// Scratch (device globals; no allocation allowed)
// ----------------------------------------------------------------------------
__device__ __align__(16) __half g_m_h[4u * QQ * DD];   // 64 MB fp16 mem
__device__ __align__(16) __half g_x_h[4 * BB * DD];    // fp16 X
__device__ float g_scale[NCOMBO * BB];                 // 1/(ni*nj*T)

// ----------------------------------------------------------------------------
// PTX helpers (sm_103-safe: mma.sync / ldmatrix / cp.async only)
// ----------------------------------------------------------------------------
__device__ __forceinline__ uint32_t smem_to_u32(const void* p) {
    uint32_t a;
    asm("{ .reg .u64 t; cvta.to.shared.u64 t, %1; cvt.u32.u64 %0, t; }" : "=r"(a) : "l"(p));
    return a;
}

__device__ __forceinline__ void cp_async16(uint32_t saddr, const void* gaddr) {
    asm volatile("cp.async.cg.shared.global [%0], [%1], 16;" :: "r"(saddr), "l"(gaddr));
}
__device__ __forceinline__ void cp_commit() {
    asm volatile("cp.async.commit_group;" ::: "memory");
}
template <int N>
__device__ __forceinline__ void cp_wait() {
    asm volatile("cp.async.wait_group %0;" :: "n"(N) : "memory");
}

__device__ __forceinline__ void ldsm_x4(uint32_t* r, uint32_t addr) {
    asm volatile("ldmatrix.sync.aligned.m8n8.x4.shared.b16 {%0,%1,%2,%3}, [%4];"
                 : "=r"(r[0]), "=r"(r[1]), "=r"(r[2]), "=r"(r[3]) : "r"(addr));
}

__device__ __forceinline__ void mma_f16(float* d, const uint32_t* a, const uint32_t* b) {
    asm volatile(
        "mma.sync.aligned.m16n8k16.row.col.f32.f16.f16.f32 "
        "{%0,%1,%2,%3}, {%4,%5,%6,%7}, {%8,%9}, {%0,%1,%2,%3};"
        : "+f"(d[0]), "+f"(d[1]), "+f"(d[2]), "+f"(d[3])
        : "r"(a[0]), "r"(a[1]), "r"(a[2]), "r"(a[3]), "r"(b[0]), "r"(b[1]));
}

// ----------------------------------------------------------------------------
// Small helpers
// ----------------------------------------------------------------------------
__device__ __forceinline__ const float* sel4(int v, const float* a, const float* b,
                                             const float* c, const float* d) {
    return v == 0 ? a : (v == 1 ? b : (v == 2 ? c : d));
}

// ----------------------------------------------------------------------------
// k_prep: merged prep (all parts independent):
//   blocks [0, 16384)      : mem -> fp16 scratch (v = b>>12)
//   blocks [16384, 16512)  : X -> fp16 scratch
//   blocks [16512, 17024)  : Y -> tail of new_mem
//   blocks [17024, 17536)  : self-dots + norms + scales (one warp per row)
// ----------------------------------------------------------------------------
__global__ void k_prep(const float* __restrict__ x0, const float* __restrict__ x1,
                       const float* __restrict__ x2, const float* __restrict__ x3,
                       const float* __restrict__ y0, const float* __restrict__ y1,
                       const float* __restrict__ y2, const float* __restrict__ y3,
                       const float* __restrict__ m0, const float* __restrict__ m1,
                       const float* __restrict__ m2, const float* __restrict__ m3,
                       float* __restrict__ out, float* __restrict__ out_mem) {
    const int b = blockIdx.x;
    const int t = threadIdx.x;
    if (b < 16384) {
        // mem -> fp16
        int v = b >> 12, bx = b & 4095;
        int idx = (bx * 256 + t) * 2;                 // float4 index, 2 per thread
        const float4* src = reinterpret_cast<const float4*>(sel4(v, m0, m1, m2, m3));
        float4 f0 = src[idx + 0];
        float4 f1 = src[idx + 1];
        __half2 h0 = __floats2half2_rn(f0.x, f0.y);
        __half2 h1 = __floats2half2_rn(f0.z, f0.w);
        __half2 h2 = __floats2half2_rn(f1.x, f1.y);
        __half2 h3 = __floats2half2_rn(f1.z, f1.w);
        uint4 pk;
        pk.x = *reinterpret_cast<uint32_t*>(&h0);
        pk.y = *reinterpret_cast<uint32_t*>(&h1);
        pk.z = *reinterpret_cast<uint32_t*>(&h2);
        pk.w = *reinterpret_cast<uint32_t*>(&h3);
        reinterpret_cast<uint4*>(g_m_h + (size_t)v * QQ * DD)[idx / 2] = pk;
    } else if (b < 16512) {
        // X -> fp16
        int r = b - 16384;
        int v = r >> 5, bx = r & 31;
        int idx = bx * 1024 + t * 4;                  // float4 index
        const float4* src = reinterpret_cast<const float4*>(sel4(v, x0, x1, x2, x3));
        uint4 pk[2];
#pragma unroll
        for (int g = 0; g < 2; g++) {
            float4 f0 = src[idx + g * 2 + 0];
            float4 f1 = src[idx + g * 2 + 1];
            __half2 h0 = __floats2half2_rn(f0.x, f0.y);
            __half2 h1 = __floats2half2_rn(f0.z, f0.w);
            __half2 h2 = __floats2half2_rn(f1.x, f1.y);
            __half2 h3 = __floats2half2_rn(f1.z, f1.w);
            pk[g].x = *reinterpret_cast<uint32_t*>(&h0);
            pk[g].y = *reinterpret_cast<uint32_t*>(&h1);
            pk[g].z = *reinterpret_cast<uint32_t*>(&h2);
            pk[g].w = *reinterpret_cast<uint32_t*>(&h3);
        }
        uint4* dst = reinterpret_cast<uint4*>(g_x_h + (size_t)v * BB * DD);
        dst[idx / 2 + 0] = pk[0];
        dst[idx / 2 + 1] = pk[1];
    } else if (b < 17024) {
        // Y -> tail of new_mem
        int r = b - 16512;
        int v = r >> 7, bx = r & 127;
        int idx = bx * 256 + t;                       // < 32768 float4 per view
        float4 f = reinterpret_cast<const float4*>(sel4(v, y0, y1, y2, y3))[idx];
        reinterpret_cast<float4*>(out_mem)[(size_t)v * (QQ * DD / 4) + (size_t)(QQ - BB) * (DD / 4) + idx] = f;
    } else {
        // self-dots + norms + scales
        int gw = (b - 17024) * 8 + (t >> 5);          // < 4096
        int lane = t & 31;
        int c = gw >> 9, row = gw & (BB - 1);
        int i = d_CI[c], j = d_CJ[c];
        const float* xi = sel4(i, x0, x1, x2, x3) + (size_t)row * DD;
        const float* xj = sel4(j, x0, x1, x2, x3) + (size_t)row * DD;
        float s = 0.f, ni = 0.f, nj = 0.f;
#pragma unroll
        for (int k = 0; k < 8; k++) {
            float a = xi[lane + k * 32], d = xj[lane + k * 32];
            s = fmaf(a, d, s);
            ni = fmaf(a, a, ni);
            nj = fmaf(d, d, nj);
        }
#pragma unroll
        for (int o = 16; o; o >>= 1) {
            s  += __shfl_xor_sync(0xffffffffu, s, o);
            ni += __shfl_xor_sync(0xffffffffu, ni, o);
            nj += __shfl_xor_sync(0xffffffffu, nj, o);
        }
        if (lane == 0) {
            float sc = 1.0f / (sqrtf(ni) * sqrtf(nj) * 0.07f);
            g_scale[c * BB + row] = sc;
            out[(size_t)c * BB * ROWL + (size_t)row * ROWL] = __expf(s * sc);
        }
    }
}

// ----------------------------------------------------------------------------
// k_gemm: single-pass fp16 mma.sync GEMM + smem-transposed exp epilogue
//         + fused FIFO copy.
// Block tile M=128 x N=128 (R8 traffic), K=256 in 4 chunks of 64,
// cp.async double-buffered. 16 warps: 4 (m) x 4 (n); warp tile 32x32.
// 512 threads, 2 CTAs/SM -> 32 warps/SM.
// ----------------------------------------------------------------------------
#define TS_ROWB   144
#define TILE_B    (128 * TS_ROWB)          // 18432
#define BUF_B     (2 * TILE_B)             // 36864 (A, B)
#define GEMM_SMEM (2 * BUF_B)              // 73728 (>= 128*132*4 = 67584)
#define EPI_STRIDE 132
#define CPY_PER_CTA 1008
#define CPY_PER_VIEW ((QQ - BB) * DD / 4)  // 2064384 float4

__global__ void __launch_bounds__(512, 2) k_gemm(float* __restrict__ out,
                                                 const float* __restrict__ m0,
                                                 const float* __restrict__ m1,
                                                 const float* __restrict__ m2,
                                                 const float* __restrict__ m3,
                                                 float* __restrict__ out_mem) {
    extern __shared__ char smem[];
    const uint32_t sb = smem_to_u32(smem);
    const int tid = threadIdx.x, lane = tid & 31, wid = tid >> 5;
    const int wm = wid & 3, wn = wid >> 2;
    const int cm = blockIdx.x;
    const int c = cm >> 2, mtile = cm & 3, ntile = blockIdx.y;
    const int i = d_CI[c], j = d_CJ[c];

    const __half* srcA = g_x_h + ((size_t)i * BB + mtile * 128) * DD;
    const __half* srcB = g_m_h + ((size_t)j * QQ + (size_t)ntile * 128) * DD;

    // per-thread load slots: 2 uint4 per tile (1024 x 16B units per tile)
    const int l_seg = tid & 7;

    auto issue_chunk = [&](int kc, int buf) {
        uint32_t sbase = sb + buf * BUF_B;
#pragma unroll
        for (int r = 0; r < 2; r++) {
            int row = (tid + r * 512) >> 3;
            const __half* gA = srcA + (size_t)row * DD + kc * 64 + l_seg * 8;
            const __half* gB = srcB + (size_t)row * DD + kc * 64 + l_seg * 8;
            uint32_t soff = row * TS_ROWB + l_seg * 16;
            cp_async16(sbase + soff, gA);
            cp_async16(sbase + TILE_B + soff, gB);
        }
        cp_commit();
    };

    issue_chunk(0, 0);

    // ---- fused FIFO shift copy (overlaps with first cp.async chunk) ----
    {
        const int gid = blockIdx.y * 32 + blockIdx.x;          // 0..8191
        int u0 = gid * CPY_PER_CTA + tid;
#pragma unroll
        for (int g = 0; g < 2; g++) {
            int u = u0 + g * 512;
            if (g < 1 || u < (gid + 1) * CPY_PER_CTA) {
                int v = u / CPY_PER_VIEW;
                int rem = u - v * CPY_PER_VIEW;
                const float4* s4 = reinterpret_cast<const float4*>(sel4(v, m0, m1, m2, m3));
                float4 f = s4[BB * (DD / 4) + rem];
                reinterpret_cast<float4*>(out_mem)[(size_t)v * (QQ * DD / 4) + rem] = f;
            }
        }
    }

    float acc[2][4][4];
#pragma unroll
    for (int a = 0; a < 2; a++)
#pragma unroll
        for (int b = 0; b < 4; b++)
#pragma unroll
            for (int k = 0; k < 4; k++) acc[a][b][k] = 0.f;

    // ldmatrix base offsets (within a buffer)
    const uint32_t a_lane_off = (uint32_t)((lane & 15) * TS_ROWB + (lane >> 4) * 16);
    const uint32_t b_lane_off = (uint32_t)(((lane & 7) + ((lane >> 4) << 3)) * TS_ROWB
                                           + (((lane >> 3) & 1) * 16));

#pragma unroll 1
    for (int kc = 0; kc < 4; kc++) {
        if (kc < 3) issue_chunk(kc + 1, (kc + 1) & 1);
        if (kc < 3) cp_wait<1>(); else cp_wait<0>();
        __syncthreads();

        const uint32_t bufb = sb + (kc & 1) * BUF_B;
        const uint32_t aT = bufb + (wm * 32) * TS_ROWB + a_lane_off;
        const uint32_t bT = bufb + TILE_B + (wn * 32) * TS_ROWB + b_lane_off;

#pragma unroll
        for (int step = 0; step < 4; step++) {
            const uint32_t koff = step * 32;   // 16 fp16 = 32 bytes
            uint32_t bh[8];
            ldsm_x4(bh + 0, bT + koff);                       // n 0-15 (local)
            ldsm_x4(bh + 4, bT + 16 * TS_ROWB + koff);        // n 16-31
#pragma unroll
            for (int mi = 0; mi < 2; mi++) {
                uint32_t ah[4];
                ldsm_x4(ah, aT + mi * 16 * TS_ROWB + koff);
#pragma unroll
                for (int ni = 0; ni < 4; ni++)
                    mma_f16(acc[mi][ni], ah, bh + ni * 2);
            }
        }
        __syncthreads();
    }

    // ---- Epilogue: exp in regs -> smem stage (128 x 132 fp32) -> coalesced STG
    float* sout = reinterpret_cast<float*>(smem);
    const int r0 = lane >> 2;
    const int cpair = (lane & 3) * 2;
#pragma unroll
    for (int mi = 0; mi < 2; mi++) {
        const int lrow0 = wm * 32 + mi * 16 + r0;    // local row 0..127
        const int grow0 = mtile * 128 + lrow0;
        const float scl0 = g_scale[c * BB + grow0];
        const float scl1 = g_scale[c * BB + grow0 + 8];
#pragma unroll
        for (int ni = 0; ni < 4; ni++) {
            const int col = wn * 32 + ni * 8 + cpair;
            sout[lrow0 * EPI_STRIDE + col + 0]       = __expf(acc[mi][ni][0] * scl0);
            sout[lrow0 * EPI_STRIDE + col + 1]       = __expf(acc[mi][ni][1] * scl0);
            sout[(lrow0 + 8) * EPI_STRIDE + col + 0] = __expf(acc[mi][ni][2] * scl1);
            sout[(lrow0 + 8) * EPI_STRIDE + col + 1] = __expf(acc[mi][ni][3] * scl1);
        }
    }
    __syncthreads();

    // drain: warp writes 32 consecutive floats per instruction (coalesced)
    const size_t ocol = 1 + (size_t)ntile * 128;
#pragma unroll 8
    for (int it = 0; it < 32; it++) {
        int flat = it * 512 + tid;                 // 0..16383
        int row = flat >> 7;
        int col = flat & 127;
        float v = sout[row * EPI_STRIDE + col];
        int grow = mtile * 128 + row;
        out[((size_t)c * BB + grow) * ROWL + ocol + col] = v;
    }
}

// ----------------------------------------------------------------------------
// kernel_launch — input order detected from in_sizes (interleaved vs grouped)
// ----------------------------------------------------------------------------
extern "C" void kernel_launch(void* const* d_in, const int* in_sizes, int n_in,
                              void* d_out, int out_size) {
    (void)n_in; (void)out_size;
    const float* x[4]; const float* y[4]; const float* m[4];
    const bool interleaved = (in_sizes[2] == QQ * DD);
    for (int v = 0; v < 4; v++) {
        if (interleaved) {
            x[v] = (const float*)d_in[3 * v + 0];
            y[v] = (const float*)d_in[3 * v + 1];
            m[v] = (const float*)d_in[3 * v + 2];
        } else {
            x[v] = (const float*)d_in[v];
            y[v] = (const float*)d_in[4 + v];
            m[v] = (const float*)d_in[8 + v];
        }
    }
    float* out = (float*)d_out;
    float* out_mem = out + (size_t)NCOMBO * BB * ROWL;

    cudaFuncSetAttribute(k_gemm, cudaFuncAttributeMaxDynamicSharedMemorySize, GEMM_SMEM);

    k_prep<<<17536, 256>>>(x[0], x[1], x[2], x[3],
                           y[0], y[1], y[2], y[3],
                           m[0], m[1], m[2], m[3], out, out_mem);
    k_gemm<<<dim3(32, 256), 512, GEMM_SMEM>>>(out, m[0], m[1], m[2], m[3], out_mem);
}

// round 13
// speedup vs baseline: 1.1539x; 1.0802x over previous
#include <cuda_runtime.h>
#include <cuda_fp16.h>
#include <cstdint>
#include <cstddef>

// ----------------------------------------------------------------------------
// Problem constants
// ----------------------------------------------------------------------------
#define BB   512
#define QQ   32768
#define DD   256
#define ROWL 32769            // 1 + Q
#define NCOMBO 8

__constant__ int d_CI[8] = {0, 0, 0, 1, 1, 2, 2, 3};
__constant__ int d_CJ[8] = {1, 2, 3, 0, 2, 0, 1, 0};

// ----------------------------------------------------------------------------
// Scratch (device globals; no allocation allowed)
// ----------------------------------------------------------------------------
__device__ __align__(16) __half g_m_h[4u * QQ * DD];   // 64 MB fp16 mem
__device__ __align__(16) __half g_x_h[4 * BB * DD];    // fp16 X
__device__ float g_scale[NCOMBO * BB];                 // 1/(ni*nj*T)

// ----------------------------------------------------------------------------
// PTX helpers (sm_103-safe: mma.sync / ldmatrix / cp.async only)
// ----------------------------------------------------------------------------
__device__ __forceinline__ uint32_t smem_to_u32(const void* p) {
    uint32_t a;
    asm("{ .reg .u64 t; cvta.to.shared.u64 t, %1; cvt.u32.u64 %0, t; }" : "=r"(a) : "l"(p));
    return a;
}

__device__ __forceinline__ void cp_async16(uint32_t saddr, const void* gaddr) {
    asm volatile("cp.async.cg.shared.global [%0], [%1], 16;" :: "r"(saddr), "l"(gaddr));
}
__device__ __forceinline__ void cp_commit() {
    asm volatile("cp.async.commit_group;" ::: "memory");
}
template <int N>
__device__ __forceinline__ void cp_wait() {
    asm volatile("cp.async.wait_group %0;" :: "n"(N) : "memory");
}

__device__ __forceinline__ void ldsm_x4(uint32_t* r, uint32_t addr) {
    asm volatile("ldmatrix.sync.aligned.m8n8.x4.shared.b16 {%0,%1,%2,%3}, [%4];"
                 : "=r"(r[0]), "=r"(r[1]), "=r"(r[2]), "=r"(r[3]) : "r"(addr));
}

__device__ __forceinline__ void mma_f16(float* d, const uint32_t* a, const uint32_t* b) {
    asm volatile(
        "mma.sync.aligned.m16n8k16.row.col.f32.f16.f16.f32 "
        "{%0,%1,%2,%3}, {%4,%5,%6,%7}, {%8,%9}, {%0,%1,%2,%3};"
        : "+f"(d[0]), "+f"(d[1]), "+f"(d[2]), "+f"(d[3])
        : "r"(a[0]), "r"(a[1]), "r"(a[2]), "r"(a[3]), "r"(b[0]), "r"(b[1]));
}

// ----------------------------------------------------------------------------
// Small helpers
// ----------------------------------------------------------------------------
__device__ __forceinline__ const float* sel4(int v, const float* a, const float* b,
                                             const float* c, const float* d) {
    return v == 0 ? a : (v == 1 ? b : (v == 2 ? c : d));
}

// ----------------------------------------------------------------------------
// k_prep: merged prep (all parts independent):
//   blocks [0, 16384)      : mem -> fp16 scratch (v = b>>12)
//   blocks [16384, 16512)  : X -> fp16 scratch
//   blocks [16512, 17024)  : Y -> tail of new_mem
//   blocks [17024, 17536)  : self-dots + norms + scales (one warp per row)
// ----------------------------------------------------------------------------
__global__ void k_prep(const float* __restrict__ x0, const float* __restrict__ x1,
                       const float* __restrict__ x2, const float* __restrict__ x3,
                       const float* __restrict__ y0, const float* __restrict__ y1,
                       const float* __restrict__ y2, const float* __restrict__ y3,
                       const float* __restrict__ m0, const float* __restrict__ m1,
                       const float* __restrict__ m2, const float* __restrict__ m3,
                       float* __restrict__ out, float* __restrict__ out_mem) {
    const int b = blockIdx.x;
    const int t = threadIdx.x;
    if (b < 16384) {
        // mem -> fp16
        int v = b >> 12, bx = b & 4095;
        int idx = (bx * 256 + t) * 2;                 // float4 index, 2 per thread
        const float4* src = reinterpret_cast<const float4*>(sel4(v, m0, m1, m2, m3));
        float4 f0 = src[idx + 0];
        float4 f1 = src[idx + 1];
        __half2 h0 = __floats2half2_rn(f0.x, f0.y);
        __half2 h1 = __floats2half2_rn(f0.z, f0.w);
        __half2 h2 = __floats2half2_rn(f1.x, f1.y);
        __half2 h3 = __floats2half2_rn(f1.z, f1.w);
        uint4 pk;
        pk.x = *reinterpret_cast<uint32_t*>(&h0);
        pk.y = *reinterpret_cast<uint32_t*>(&h1);
        pk.z = *reinterpret_cast<uint32_t*>(&h2);
        pk.w = *reinterpret_cast<uint32_t*>(&h3);
        reinterpret_cast<uint4*>(g_m_h + (size_t)v * QQ * DD)[idx / 2] = pk;
    } else if (b < 16512) {
        // X -> fp16
        int r = b - 16384;
        int v = r >> 5, bx = r & 31;
        int idx = bx * 1024 + t * 4;                  // float4 index
        const float4* src = reinterpret_cast<const float4*>(sel4(v, x0, x1, x2, x3));
        uint4 pk[2];
#pragma unroll
        for (int g = 0; g < 2; g++) {
            float4 f0 = src[idx + g * 2 + 0];
            float4 f1 = src[idx + g * 2 + 1];
            __half2 h0 = __floats2half2_rn(f0.x, f0.y);
            __half2 h1 = __floats2half2_rn(f0.z, f0.w);
            __half2 h2 = __floats2half2_rn(f1.x, f1.y);
            __half2 h3 = __floats2half2_rn(f1.z, f1.w);
            pk[g].x = *reinterpret_cast<uint32_t*>(&h0);
            pk[g].y = *reinterpret_cast<uint32_t*>(&h1);
            pk[g].z = *reinterpret_cast<uint32_t*>(&h2);
            pk[g].w = *reinterpret_cast<uint32_t*>(&h3);
        }
        uint4* dst = reinterpret_cast<uint4*>(g_x_h + (size_t)v * BB * DD);
        dst[idx / 2 + 0] = pk[0];
        dst[idx / 2 + 1] = pk[1];
    } else if (b < 17024) {
        // Y -> tail of new_mem
        int r = b - 16512;
        int v = r >> 7, bx = r & 127;
        int idx = bx * 256 + t;                       // < 32768 float4 per view
        float4 f = reinterpret_cast<const float4*>(sel4(v, y0, y1, y2, y3))[idx];
        reinterpret_cast<float4*>(out_mem)[(size_t)v * (QQ * DD / 4) + (size_t)(QQ - BB) * (DD / 4) + idx] = f;
    } else {
        // self-dots + norms + scales
        int gw = (b - 17024) * 8 + (t >> 5);          // < 4096
        int lane = t & 31;
        int c = gw >> 9, row = gw & (BB - 1);
        int i = d_CI[c], j = d_CJ[c];
        const float* xi = sel4(i, x0, x1, x2, x3) + (size_t)row * DD;
        const float* xj = sel4(j, x0, x1, x2, x3) + (size_t)row * DD;
        float s = 0.f, ni = 0.f, nj = 0.f;
#pragma unroll
        for (int k = 0; k < 8; k++) {
            float a = xi[lane + k * 32], d = xj[lane + k * 32];
            s = fmaf(a, d, s);
            ni = fmaf(a, a, ni);
            nj = fmaf(d, d, nj);
        }
#pragma unroll
        for (int o = 16; o; o >>= 1) {
            s  += __shfl_xor_sync(0xffffffffu, s, o);
            ni += __shfl_xor_sync(0xffffffffu, ni, o);
            nj += __shfl_xor_sync(0xffffffffu, nj, o);
        }
        if (lane == 0) {
            float sc = 1.0f / (sqrtf(ni) * sqrtf(nj) * 0.07f);
            g_scale[c * BB + row] = sc;
            out[(size_t)c * BB * ROWL + (size_t)row * ROWL] = __expf(s * sc);
        }
    }
}

// ----------------------------------------------------------------------------
// k_gemm: single-pass fp16 mma.sync GEMM + smem-transposed exp epilogue
//         + fused FIFO copy. R8 shape, triple-buffered pipeline (1 sync/chunk).
// Block tile M=128 x N=128, K=256 in 4 chunks of 64.
// 8 warps: 2 (m) x 4 (n); warp tile 64x32. 256 threads, 2 CTAs/SM.
// ----------------------------------------------------------------------------
#define TS_ROWB   144
#define TILE_B    (128 * TS_ROWB)          // 18432
#define BUF_B     (2 * TILE_B)             // 36864 (A, B)
#define GEMM_SMEM (3 * BUF_B)              // 110592 (>= 128*132*4 = 67584)
#define EPI_STRIDE 132
#define CPY_PER_CTA 1008
#define CPY_PER_VIEW ((QQ - BB) * DD / 4)  // 2064384 float4

__global__ void __launch_bounds__(256, 2) k_gemm(float* __restrict__ out,
                                                 const float* __restrict__ m0,
                                                 const float* __restrict__ m1,
                                                 const float* __restrict__ m2,
                                                 const float* __restrict__ m3,
                                                 float* __restrict__ out_mem) {
    extern __shared__ char smem[];
    const uint32_t sb = smem_to_u32(smem);
    const int tid = threadIdx.x, lane = tid & 31, wid = tid >> 5;
    const int wm = wid & 1, wn = wid >> 1;
    const int cm = blockIdx.x;
    const int c = cm >> 2, mtile = cm & 3, ntile = blockIdx.y;
    const int i = d_CI[c], j = d_CJ[c];

    const __half* srcA = g_x_h + ((size_t)i * BB + mtile * 128) * DD;
    const __half* srcB = g_m_h + ((size_t)j * QQ + (size_t)ntile * 128) * DD;

    // per-thread load slots: 4 uint4 per tile, row = idx/8, seg = idx%8
    const int l_row[4] = { (tid + 0 * 256) >> 3, (tid + 1 * 256) >> 3,
                           (tid + 2 * 256) >> 3, (tid + 3 * 256) >> 3 };
    const int l_seg = tid & 7;

    auto issue_chunk = [&](int kc, int buf) {
        uint32_t sbase = sb + buf * BUF_B;
#pragma unroll
        for (int r = 0; r < 4; r++) {
            const __half* gA = srcA + (size_t)l_row[r] * DD + kc * 64 + l_seg * 8;
            const __half* gB = srcB + (size_t)l_row[r] * DD + kc * 64 + l_seg * 8;
            uint32_t soff = l_row[r] * TS_ROWB + l_seg * 16;
            cp_async16(sbase + soff, gA);
            cp_async16(sbase + TILE_B + soff, gB);
        }
        cp_commit();
    };

    issue_chunk(0, 0);

    // ---- fused FIFO shift copy (overlaps with first cp.async chunk) ----
    {
        const int gid = blockIdx.y * 32 + blockIdx.x;          // 0..8191
        int u0 = gid * CPY_PER_CTA + tid;
#pragma unroll
        for (int g = 0; g < 4; g++) {
            int u = u0 + g * 256;
            if (g < 3 || u < (gid + 1) * CPY_PER_CTA) {
                int v = u / CPY_PER_VIEW;
                int rem = u - v * CPY_PER_VIEW;
                const float4* s4 = reinterpret_cast<const float4*>(sel4(v, m0, m1, m2, m3));
                float4 f = s4[BB * (DD / 4) + rem];
                reinterpret_cast<float4*>(out_mem)[(size_t)v * (QQ * DD / 4) + rem] = f;
            }
        }
    }

    issue_chunk(1, 1);

    float acc[4][4][4];
#pragma unroll
    for (int a = 0; a < 4; a++)
#pragma unroll
        for (int b = 0; b < 4; b++)
#pragma unroll
            for (int k = 0; k < 4; k++) acc[a][b][k] = 0.f;

    // ldmatrix base offsets (within a buffer)
    const uint32_t a_lane_off = (uint32_t)((lane & 15) * TS_ROWB + (lane >> 4) * 16);
    const uint32_t b_lane_off = (uint32_t)(((lane & 7) + ((lane >> 4) << 3)) * TS_ROWB
                                           + (((lane >> 3) & 1) * 16));

#pragma unroll 1
    for (int kc = 0; kc < 4; kc++) {
        if (kc < 3) cp_wait<1>(); else cp_wait<0>();
        __syncthreads();                     // chunk kc visible + guards rewrite
        if (kc < 2) issue_chunk(kc + 2, (kc + 2) % 3);

        const uint32_t bufb = sb + (kc % 3) * BUF_B;
        const uint32_t aT = bufb + (wm * 64) * TS_ROWB + a_lane_off;
        const uint32_t bT = bufb + TILE_B + (wn * 32) * TS_ROWB + b_lane_off;

#pragma unroll
        for (int step = 0; step < 4; step++) {
            const uint32_t koff = step * 32;   // 16 fp16 = 32 bytes
            uint32_t bh[8];
            ldsm_x4(bh + 0, bT + koff);                       // n 0-15
            ldsm_x4(bh + 4, bT + 16 * TS_ROWB + koff);        // n 16-31
#pragma unroll
            for (int mi = 0; mi < 4; mi++) {
                uint32_t ah[4];
                ldsm_x4(ah, aT + mi * 16 * TS_ROWB + koff);
#pragma unroll
                for (int ni = 0; ni < 4; ni++)
                    mma_f16(acc[mi][ni], ah, bh + ni * 2);
            }
        }
    }
    __syncthreads();                         // all reads done before epilogue reuse

    // ---- Epilogue: exp in regs -> smem stage (128 x 132 fp32) -> coalesced STG
    float* sout = reinterpret_cast<float*>(smem);
    const int r0 = lane >> 2;
    const int cpair = (lane & 3) * 2;
#pragma unroll
    for (int mi = 0; mi < 4; mi++) {
        const int lrow0 = wm * 64 + mi * 16 + r0;    // local row 0..127
        const int grow0 = mtile * 128 + lrow0;
        const float scl0 = g_scale[c * BB + grow0];
        const float scl1 = g_scale[c * BB + grow0 + 8];
#pragma unroll
        for (int ni = 0; ni < 4; ni++) {
            const int col = wn * 32 + ni * 8 + cpair;
            sout[lrow0 * EPI_STRIDE + col + 0]       = __expf(acc[mi][ni][0] * scl0);
            sout[lrow0 * EPI_STRIDE + col + 1]       = __expf(acc[mi][ni][1] * scl0);
            sout[(lrow0 + 8) * EPI_STRIDE + col + 0] = __expf(acc[mi][ni][2] * scl1);
            sout[(lrow0 + 8) * EPI_STRIDE + col + 1] = __expf(acc[mi][ni][3] * scl1);
        }
    }
    __syncthreads();

    // drain: warp writes 32 consecutive floats per instruction (coalesced)
    const size_t ocol = 1 + (size_t)ntile * 128;
#pragma unroll 8
    for (int it = 0; it < 64; it++) {
        int flat = it * 256 + tid;                 // 0..16383
        int row = flat >> 7;
        int col = flat & 127;
        float v = sout[row * EPI_STRIDE + col];
        int grow = mtile * 128 + row;
        out[((size_t)c * BB + grow) * ROWL + ocol + col] = v;
    }
}

// ----------------------------------------------------------------------------
// kernel_launch — input order detected from in_sizes (interleaved vs grouped)
// ----------------------------------------------------------------------------
extern "C" void kernel_launch(void* const* d_in, const int* in_sizes, int n_in,
                              void* d_out, int out_size) {
    (void)n_in; (void)out_size;
    const float* x[4]; const float* y[4]; const float* m[4];
    const bool interleaved = (in_sizes[2] == QQ * DD);
    for (int v = 0; v < 4; v++) {
        if (interleaved) {
            x[v] = (const float*)d_in[3 * v + 0];
            y[v] = (const float*)d_in[3 * v + 1];
            m[v] = (const float*)d_in[3 * v + 2];
        } else {
            x[v] = (const float*)d_in[v];
            y[v] = (const float*)d_in[4 + v];
            m[v] = (const float*)d_in[8 + v];
        }
    }
    float* out = (float*)d_out;
    float* out_mem = out + (size_t)NCOMBO * BB * ROWL;

    cudaFuncSetAttribute(k_gemm, cudaFuncAttributeMaxDynamicSharedMemorySize, GEMM_SMEM);

    k_prep<<<17536, 256>>>(x[0], x[1], x[2], x[3],
                           y[0], y[1], y[2], y[3],
                           m[0], m[1], m[2], m[3], out, out_mem);
    k_gemm<<<dim3(32, 256), 256, GEMM_SMEM>>>(out, m[0], m[1], m[2], m[3], out_mem);
}

// round 14
// speedup vs baseline: 1.1678x; 1.0120x over previous
#include <cuda_runtime.h>
#include <cuda_fp16.h>
#include <cstdint>
#include <cstddef>

// ----------------------------------------------------------------------------
// Problem constants
// ----------------------------------------------------------------------------
#define BB   512
#define QQ   32768
#define DD   256
#define ROWL 32769            // 1 + Q
#define NCOMBO 8

__constant__ int d_CI[8] = {0, 0, 0, 1, 1, 2, 2, 3};
__constant__ int d_CJ[8] = {1, 2, 3, 0, 2, 0, 1, 0};

// ----------------------------------------------------------------------------
// Scratch (device globals; no allocation allowed)
// ----------------------------------------------------------------------------
__device__ __align__(16) __half g_m_h[4u * QQ * DD];   // 64 MB fp16 mem
__device__ __align__(16) __half g_x_h[4 * BB * DD];    // fp16 X
__device__ float g_scale[NCOMBO * BB];                 // 1/(ni*nj*T)

// ----------------------------------------------------------------------------
// PTX helpers (sm_103-safe: mma.sync / ldmatrix / cp.async / mbarrier)
// ----------------------------------------------------------------------------
__device__ __forceinline__ uint32_t smem_to_u32(const void* p) {
    uint32_t a;
    asm("{ .reg .u64 t; cvta.to.shared.u64 t, %1; cvt.u32.u64 %0, t; }" : "=r"(a) : "l"(p));
    return a;
}

__device__ __forceinline__ void cp_async16(uint32_t saddr, const void* gaddr) {
    asm volatile("cp.async.cg.shared.global [%0], [%1], 16;" :: "r"(saddr), "l"(gaddr));
}

__device__ __forceinline__ void mbar_init(uint32_t mbar, uint32_t cnt) {
    asm volatile("mbarrier.init.shared.b64 [%0], %1;" :: "r"(mbar), "r"(cnt) : "memory");
}

// arrive-on-completion of this thread's prior cp.asyncs (no expected-count inc)
__device__ __forceinline__ void cp_arrive(uint32_t mbar) {
    asm volatile("cp.async.mbarrier.arrive.noinc.shared.b64 [%0];" :: "r"(mbar) : "memory");
}

__device__ __forceinline__ void mbar_wait(uint32_t mbar, uint32_t parity) {
    asm volatile(
        "{\n\t.reg .pred P1;\n\t"
        "WAIT_%=:\n\t"
        "mbarrier.try_wait.parity.shared.b64 P1, [%0], %1;\n\t"
        "@P1 bra.uni DONE_%=;\n\t"
        "bra.uni WAIT_%=;\n\t"
        "DONE_%=:\n\t}"
        :: "r"(mbar), "r"(parity) : "memory");
}

__device__ __forceinline__ void ldsm_x4(uint32_t* r, uint32_t addr) {
    asm volatile("ldmatrix.sync.aligned.m8n8.x4.shared.b16 {%0,%1,%2,%3}, [%4];"
                 : "=r"(r[0]), "=r"(r[1]), "=r"(r[2]), "=r"(r[3]) : "r"(addr));
}

__device__ __forceinline__ void mma_f16(float* d, const uint32_t* a, const uint32_t* b) {
    asm volatile(
        "mma.sync.aligned.m16n8k16.row.col.f32.f16.f16.f32 "
        "{%0,%1,%2,%3}, {%4,%5,%6,%7}, {%8,%9}, {%0,%1,%2,%3};"
        : "+f"(d[0]), "+f"(d[1]), "+f"(d[2]), "+f"(d[3])
        : "r"(a[0]), "r"(a[1]), "r"(a[2]), "r"(a[3]), "r"(b[0]), "r"(b[1]));
}

// ----------------------------------------------------------------------------
// Small helpers
// ----------------------------------------------------------------------------
__device__ __forceinline__ const float* sel4(int v, const float* a, const float* b,
                                             const float* c, const float* d) {
    return v == 0 ? a : (v == 1 ? b : (v == 2 ? c : d));
}

// ----------------------------------------------------------------------------
// k_prep: merged prep (all parts independent):
//   blocks [0, 16384)      : mem -> fp16 scratch (v = b>>12)
//   blocks [16384, 16512)  : X -> fp16 scratch
//   blocks [16512, 17024)  : Y -> tail of new_mem
//   blocks [17024, 17536)  : self-dots + norms + scales (one warp per row)
// ----------------------------------------------------------------------------
__global__ void k_prep(const float* __restrict__ x0, const float* __restrict__ x1,
                       const float* __restrict__ x2, const float* __restrict__ x3,
                       const float* __restrict__ y0, const float* __restrict__ y1,
                       const float* __restrict__ y2, const float* __restrict__ y3,
                       const float* __restrict__ m0, const float* __restrict__ m1,
                       const float* __restrict__ m2, const float* __restrict__ m3,
                       float* __restrict__ out, float* __restrict__ out_mem) {
    const int b = blockIdx.x;
    const int t = threadIdx.x;
    if (b < 16384) {
        // mem -> fp16
        int v = b >> 12, bx = b & 4095;
        int idx = (bx * 256 + t) * 2;                 // float4 index, 2 per thread
        const float4* src = reinterpret_cast<const float4*>(sel4(v, m0, m1, m2, m3));
        float4 f0 = src[idx + 0];
        float4 f1 = src[idx + 1];
        __half2 h0 = __floats2half2_rn(f0.x, f0.y);
        __half2 h1 = __floats2half2_rn(f0.z, f0.w);
        __half2 h2 = __floats2half2_rn(f1.x, f1.y);
        __half2 h3 = __floats2half2_rn(f1.z, f1.w);
        uint4 pk;
        pk.x = *reinterpret_cast<uint32_t*>(&h0);
        pk.y = *reinterpret_cast<uint32_t*>(&h1);
        pk.z = *reinterpret_cast<uint32_t*>(&h2);
        pk.w = *reinterpret_cast<uint32_t*>(&h3);
        reinterpret_cast<uint4*>(g_m_h + (size_t)v * QQ * DD)[idx / 2] = pk;
    } else if (b < 16512) {
        // X -> fp16
        int r = b - 16384;
        int v = r >> 5, bx = r & 31;
        int idx = bx * 1024 + t * 4;                  // float4 index
        const float4* src = reinterpret_cast<const float4*>(sel4(v, x0, x1, x2, x3));
        uint4 pk[2];
#pragma unroll
        for (int g = 0; g < 2; g++) {
            float4 f0 = src[idx + g * 2 + 0];
            float4 f1 = src[idx + g * 2 + 1];
            __half2 h0 = __floats2half2_rn(f0.x, f0.y);
            __half2 h1 = __floats2half2_rn(f0.z, f0.w);
            __half2 h2 = __floats2half2_rn(f1.x, f1.y);
            __half2 h3 = __floats2half2_rn(f1.z, f1.w);
            pk[g].x = *reinterpret_cast<uint32_t*>(&h0);
            pk[g].y = *reinterpret_cast<uint32_t*>(&h1);
            pk[g].z = *reinterpret_cast<uint32_t*>(&h2);
            pk[g].w = *reinterpret_cast<uint32_t*>(&h3);
        }
        uint4* dst = reinterpret_cast<uint4*>(g_x_h + (size_t)v * BB * DD);
        dst[idx / 2 + 0] = pk[0];
        dst[idx / 2 + 1] = pk[1];
    } else if (b < 17024) {
        // Y -> tail of new_mem
        int r = b - 16512;
        int v = r >> 7, bx = r & 127;
        int idx = bx * 256 + t;                       // < 32768 float4 per view
        float4 f = reinterpret_cast<const float4*>(sel4(v, y0, y1, y2, y3))[idx];
        reinterpret_cast<float4*>(out_mem)[(size_t)v * (QQ * DD / 4) + (size_t)(QQ - BB) * (DD / 4) + idx] = f;
    } else {
        // self-dots + norms + scales
        int gw = (b - 17024) * 8 + (t >> 5);          // < 4096
        int lane = t & 31;
        int c = gw >> 9, row = gw & (BB - 1);
        int i = d_CI[c], j = d_CJ[c];
        const float* xi = sel4(i, x0, x1, x2, x3) + (size_t)row * DD;
        const float* xj = sel4(j, x0, x1, x2, x3) + (size_t)row * DD;
        float s = 0.f, ni = 0.f, nj = 0.f;
#pragma unroll
        for (int k = 0; k < 8; k++) {
            float a = xi[lane + k * 32], d = xj[lane + k * 32];
            s = fmaf(a, d, s);
            ni = fmaf(a, a, ni);
            nj = fmaf(d, d, nj);
        }
#pragma unroll
        for (int o = 16; o; o >>= 1) {
            s  += __shfl_xor_sync(0xffffffffu, s, o);
            ni += __shfl_xor_sync(0xffffffffu, ni, o);
            nj += __shfl_xor_sync(0xffffffffu, nj, o);
        }
        if (lane == 0) {
            float sc = 1.0f / (sqrtf(ni) * sqrtf(nj) * 0.07f);
            g_scale[c * BB + row] = sc;
            out[(size_t)c * BB * ROWL + (size_t)row * ROWL] = __expf(s * sc);
        }
    }
}

// ----------------------------------------------------------------------------
// k_gemm: single-pass fp16 mma.sync GEMM + smem-transposed exp epilogue
//         + fused FIFO copy. mbarrier pipeline: data-readiness waits instead
//         of rendezvous barriers (1 syncthreads in mainloop).
// Block tile M=128 x N=128, K=256 in 4 chunks of 64, 3 smem buffers.
// 8 warps: 2 (m) x 4 (n); warp tile 64x32. 256 threads, 2 CTAs/SM.
// ----------------------------------------------------------------------------
#define TS_ROWB   144
#define TILE_B    (128 * TS_ROWB)          // 18432
#define BUF_B     (2 * TILE_B)             // 36864 (A, B)
#define MBAR_OFF  (3 * BUF_B)              // 110592
#define GEMM_SMEM (MBAR_OFF + 32)          // 110624 (epi stage 128*132*4 fits)
#define EPI_STRIDE 132
#define CPY_PER_CTA 1008
#define CPY_PER_VIEW ((QQ - BB) * DD / 4)  // 2064384 float4

__global__ void __launch_bounds__(256, 2) k_gemm(float* __restrict__ out,
                                                 const float* __restrict__ m0,
                                                 const float* __restrict__ m1,
                                                 const float* __restrict__ m2,
                                                 const float* __restrict__ m3,
                                                 float* __restrict__ out_mem) {
    extern __shared__ char smem[];
    const uint32_t sb = smem_to_u32(smem);
    const uint32_t mb = sb + MBAR_OFF;
    const int tid = threadIdx.x, lane = tid & 31, wid = tid >> 5;
    const int wm = wid & 1, wn = wid >> 1;
    const int cm = blockIdx.x;
    const int c = cm >> 2, mtile = cm & 3, ntile = blockIdx.y;
    const int i = d_CI[c], j = d_CJ[c];

    const __half* srcA = g_x_h + ((size_t)i * BB + mtile * 128) * DD;
    const __half* srcB = g_m_h + ((size_t)j * QQ + (size_t)ntile * 128) * DD;

    // per-thread load slots: 4 uint4 per tile, row = idx/8, seg = idx%8
    const int l_row[4] = { (tid + 0 * 256) >> 3, (tid + 1 * 256) >> 3,
                           (tid + 2 * 256) >> 3, (tid + 3 * 256) >> 3 };
    const int l_seg = tid & 7;

    auto issue_chunk = [&](int kc, int buf) {
        uint32_t sbase = sb + buf * BUF_B;
#pragma unroll
        for (int r = 0; r < 4; r++) {
            const __half* gA = srcA + (size_t)l_row[r] * DD + kc * 64 + l_seg * 8;
            const __half* gB = srcB + (size_t)l_row[r] * DD + kc * 64 + l_seg * 8;
            uint32_t soff = l_row[r] * TS_ROWB + l_seg * 16;
            cp_async16(sbase + soff, gA);
            cp_async16(sbase + TILE_B + soff, gB);
        }
    };

    // init 4 single-phase mbarriers (arrive count = 256 threads)
    if (tid < 4) mbar_init(mb + tid * 8, 256);
    __syncthreads();

    issue_chunk(0, 0);
    cp_arrive(mb + 0);

    // ---- fused FIFO shift copy (overlaps with in-flight cp.async) ----
    {
        const int gid = blockIdx.y * 32 + blockIdx.x;          // 0..8191
        int u0 = gid * CPY_PER_CTA + tid;
#pragma unroll
        for (int g = 0; g < 4; g++) {
            int u = u0 + g * 256;
            if (g < 3 || u < (gid + 1) * CPY_PER_CTA) {
                int v = u / CPY_PER_VIEW;
                int rem = u - v * CPY_PER_VIEW;
                const float4* s4 = reinterpret_cast<const float4*>(sel4(v, m0, m1, m2, m3));
                float4 f = s4[BB * (DD / 4) + rem];
                reinterpret_cast<float4*>(out_mem)[(size_t)v * (QQ * DD / 4) + rem] = f;
            }
        }
    }

    issue_chunk(1, 1);
    cp_arrive(mb + 8);
    issue_chunk(2, 2);
    cp_arrive(mb + 16);

    float acc[4][4][4];
#pragma unroll
    for (int a = 0; a < 4; a++)
#pragma unroll
        for (int b = 0; b < 4; b++)
#pragma unroll
            for (int k = 0; k < 4; k++) acc[a][b][k] = 0.f;

    // ldmatrix base offsets (within a buffer)
    const uint32_t a_lane_off = (uint32_t)((lane & 15) * TS_ROWB + (lane >> 4) * 16);
    const uint32_t b_lane_off = (uint32_t)(((lane & 7) + ((lane >> 4) << 3)) * TS_ROWB
                                           + (((lane >> 3) & 1) * 16));

#pragma unroll 1
    for (int kc = 0; kc < 4; kc++) {
        mbar_wait(mb + kc * 8, 0);          // data-readiness only (no rendezvous)

        const uint32_t bufb = sb + (kc % 3) * BUF_B;
        const uint32_t aT = bufb + (wm * 64) * TS_ROWB + a_lane_off;
        const uint32_t bT = bufb + TILE_B + (wn * 32) * TS_ROWB + b_lane_off;

#pragma unroll
        for (int step = 0; step < 4; step++) {
            const uint32_t koff = step * 32;   // 16 fp16 = 32 bytes
            uint32_t bh[8];
            ldsm_x4(bh + 0, bT + koff);                       // n 0-15
            ldsm_x4(bh + 4, bT + 16 * TS_ROWB + koff);        // n 16-31
#pragma unroll
            for (int mi = 0; mi < 4; mi++) {
                uint32_t ah[4];
                ldsm_x4(ah, aT + mi * 16 * TS_ROWB + koff);
#pragma unroll
                for (int ni = 0; ni < 4; ni++)
                    mma_f16(acc[mi][ni], ah, bh + ni * 2);
            }
        }

        if (kc == 0) {
            __syncthreads();                 // all readers done with buf 0
            issue_chunk(3, 0);               // reuse buf 0 for chunk 3
            cp_arrive(mb + 24);
        }
    }
    __syncthreads();                         // all mainloop reads done before reuse

    // ---- Epilogue: exp in regs -> smem stage (128 x 132 fp32) -> coalesced STG
    float* sout = reinterpret_cast<float*>(smem);
    const int r0 = lane >> 2;
    const int cpair = (lane & 3) * 2;
#pragma unroll
    for (int mi = 0; mi < 4; mi++) {
        const int lrow0 = wm * 64 + mi * 16 + r0;    // local row 0..127
        const int grow0 = mtile * 128 + lrow0;
        const float scl0 = g_scale[c * BB + grow0];
        const float scl1 = g_scale[c * BB + grow0 + 8];
#pragma unroll
        for (int ni = 0; ni < 4; ni++) {
            const int col = wn * 32 + ni * 8 + cpair;   // even -> 8B aligned
            float2 p0 = make_float2(__expf(acc[mi][ni][0] * scl0),
                                    __expf(acc[mi][ni][1] * scl0));
            float2 p1 = make_float2(__expf(acc[mi][ni][2] * scl1),
                                    __expf(acc[mi][ni][3] * scl1));
            *reinterpret_cast<float2*>(&sout[lrow0 * EPI_STRIDE + col]) = p0;
            *reinterpret_cast<float2*>(&sout[(lrow0 + 8) * EPI_STRIDE + col]) = p1;
        }
    }
    __syncthreads();

    // drain: warp writes 32 consecutive floats per instruction (coalesced)
    const size_t ocol = 1 + (size_t)ntile * 128;
#pragma unroll 8
    for (int it = 0; it < 64; it++) {
        int flat = it * 256 + tid;                 // 0..16383
        int row = flat >> 7;
        int col = flat & 127;
        float v = sout[row * EPI_STRIDE + col];
        int grow = mtile * 128 + row;
        out[((size_t)c * BB + grow) * ROWL + ocol + col] = v;
    }
}

// ----------------------------------------------------------------------------
// kernel_launch — input order detected from in_sizes (interleaved vs grouped)
// ----------------------------------------------------------------------------
extern "C" void kernel_launch(void* const* d_in, const int* in_sizes, int n_in,
                              void* d_out, int out_size) {
    (void)n_in; (void)out_size;
    const float* x[4]; const float* y[4]; const float* m[4];
    const bool interleaved = (in_sizes[2] == QQ * DD);
    for (int v = 0; v < 4; v++) {
        if (interleaved) {
            x[v] = (const float*)d_in[3 * v + 0];
            y[v] = (const float*)d_in[3 * v + 1];
            m[v] = (const float*)d_in[3 * v + 2];
        } else {
            x[v] = (const float*)d_in[v];
            y[v] = (const float*)d_in[4 + v];
            m[v] = (const float*)d_in[8 + v];
        }
    }
    float* out = (float*)d_out;
    float* out_mem = out + (size_t)NCOMBO * BB * ROWL;

    cudaFuncSetAttribute(k_gemm, cudaFuncAttributeMaxDynamicSharedMemorySize, GEMM_SMEM);

    k_prep<<<17536, 256>>>(x[0], x[1], x[2], x[3],
                           y[0], y[1], y[2], y[3],
                           m[0], m[1], m[2], m[3], out, out_mem);
    k_gemm<<<dim3(32, 256), 256, GEMM_SMEM>>>(out, m[0], m[1], m[2], m[3], out_mem);
}